// round 1
// baseline (speedup 1.0000x reference)
#include <cuda_runtime.h>
#include <math.h>

#define BATCH   8
#define CHANNELS 3
#define NSRC    4096
#define MTGT    4096
#define TPB     128
#define CHUNKS  (NSRC / TPB)   // 32 source-chunks per batch
#define NBLOCKS (BATCH * CHUNKS)

// Deterministic partial sums (no atomics, no allocation)
__device__ float g_partial[NBLOCKS];

__global__ void __launch_bounds__(TPB)
nn_min_kernel(const float* __restrict__ src, const float* __restrict__ tgt)
{
    extern __shared__ float4 st[];   // MTGT float4 = 64 KB: {tx, ty, tz, t2}

    const int b     = blockIdx.x / CHUNKS;
    const int chunk = blockIdx.x % CHUNKS;

    // Stage this batch's targets into smem with precomputed |t|^2
    const float* tb = tgt + (size_t)b * CHANNELS * MTGT;
    for (int m = threadIdx.x; m < MTGT; m += TPB) {
        float tx = tb[m];
        float ty = tb[MTGT + m];
        float tz = tb[2 * MTGT + m];
        st[m] = make_float4(tx, ty, tz, fmaf(tx, tx, fmaf(ty, ty, tz * tz)));
    }
    __syncthreads();

    // One source point per thread
    const int n = chunk * TPB + threadIdx.x;
    const float* sb = src + (size_t)b * CHANNELS * NSRC;
    const float sx = sb[n];
    const float sy = sb[NSRC + n];
    const float sz = sb[2 * NSRC + n];
    const float nsx = -2.0f * sx;
    const float nsy = -2.0f * sy;
    const float nsz = -2.0f * sz;
    const float s2  = fmaf(sx, sx, fmaf(sy, sy, sz * sz));

    // 4 independent min accumulators (break FMNMX dependency chain)
    float m0 = 3.4e38f, m1 = 3.4e38f, m2 = 3.4e38f, m3 = 3.4e38f;

    #pragma unroll 4
    for (int m = 0; m < MTGT; m += 4) {
        float4 t0 = st[m + 0];
        float4 t1 = st[m + 1];
        float4 t2 = st[m + 2];
        float4 t3 = st[m + 3];

        float d0 = fmaf(t0.z, nsz, fmaf(t0.y, nsy, fmaf(t0.x, nsx, t0.w)));
        float d1 = fmaf(t1.z, nsz, fmaf(t1.y, nsy, fmaf(t1.x, nsx, t1.w)));
        float d2 = fmaf(t2.z, nsz, fmaf(t2.y, nsy, fmaf(t2.x, nsx, t2.w)));
        float d3 = fmaf(t3.z, nsz, fmaf(t3.y, nsy, fmaf(t3.x, nsx, t3.w)));

        m0 = fminf(m0, d0);
        m1 = fminf(m1, d1);
        m2 = fminf(m2, d2);
        m3 = fminf(m3, d3);
    }

    float mind = fminf(fminf(m0, m1), fminf(m2, m3)) + s2;

    // Block-level sum of min distances
    #pragma unroll
    for (int off = 16; off > 0; off >>= 1)
        mind += __shfl_down_sync(0xFFFFFFFFu, mind, off);

    __shared__ float wsum[TPB / 32];
    const int lane = threadIdx.x & 31;
    const int wid  = threadIdx.x >> 5;
    if (lane == 0) wsum[wid] = mind;
    __syncthreads();

    if (threadIdx.x == 0) {
        float s = 0.0f;
        #pragma unroll
        for (int i = 0; i < TPB / 32; i++) s += wsum[i];
        g_partial[blockIdx.x] = s;
    }
}

__global__ void finish_kernel(float* __restrict__ out)
{
    const int b = threadIdx.x;
    if (b < BATCH) {
        float s = 0.0f;
        #pragma unroll
        for (int i = 0; i < CHUNKS; i++)
            s += g_partial[b * CHUNKS + i];
        out[b] = s * (1.0f / (float)(CHANNELS * NSRC));
    }
}

extern "C" void kernel_launch(void* const* d_in, const int* in_sizes, int n_in,
                              void* d_out, int out_size)
{
    const float* src = (const float*)d_in[0];   // [B,3,N]
    const float* tgt = (const float*)d_in[1];   // [B,3,M]
    float* out = (float*)d_out;                 // [B]

    static bool attr_set = false;
    if (!attr_set) {
        cudaFuncSetAttribute(nn_min_kernel,
                             cudaFuncAttributeMaxDynamicSharedMemorySize,
                             MTGT * sizeof(float4));
        attr_set = true;
    }

    nn_min_kernel<<<NBLOCKS, TPB, MTGT * sizeof(float4)>>>(src, tgt);
    finish_kernel<<<1, 32>>>(out);
}

// round 2
// speedup vs baseline: 1.2740x; 1.2740x over previous
#include <cuda_runtime.h>
#include <math.h>

#define BATCH    8
#define NSRC     4096
#define MTGT     4096
#define TPB      128
#define SPT      4                     // sources per thread
#define SRC_PER_BLK (TPB * SPT)        // 512
#define NCHUNK   (NSRC / SRC_PER_BLK)  // 8
#define TSPLIT   4                     // target slices
#define MSLICE   (MTGT / TSPLIT)       // 1024
#define NPAIR    (MSLICE / 2)          // 512
#define NBLOCKS  (BATCH * NCHUNK * TSPLIT) // 256

// Per-(batch,slice,source) partial min. 8*4*4096 floats = 512 KB.
__device__ float g_min[BATCH * TSPLIT * NSRC];

typedef unsigned long long u64;

__device__ __forceinline__ u64 pack2(float lo, float hi) {
    u64 r;
    asm("mov.b64 %0, {%1, %2};" : "=l"(r) : "f"(lo), "f"(hi));
    return r;
}
__device__ __forceinline__ void unpack2(u64 v, float& lo, float& hi) {
    asm("mov.b64 {%0, %1}, %2;" : "=f"(lo), "=f"(hi) : "l"(v));
}
// packed dual-FMA: d = a*b + c on both 32-bit halves (SASS FFMA2)
__device__ __forceinline__ u64 ffma2(u64 a, u64 b, u64 c) {
    u64 d;
    asm("fma.rn.f32x2 %0, %1, %2, %3;" : "=l"(d) : "l"(a), "l"(b), "l"(c));
    return d;
}

__global__ void __launch_bounds__(TPB)
nn_min_kernel(const float* __restrict__ src, const float* __restrict__ tgt)
{
    // pair-interleaved targets: st[2p]={x0,x1,y0,y1}, st[2p+1]={z0,z1,w0,w1}
    __shared__ float4 st[2 * NPAIR];   // 16 KB

    const int bid   = blockIdx.x;
    const int slice = bid % TSPLIT;
    const int chunk = (bid / TSPLIT) % NCHUNK;
    const int b     = bid / (TSPLIT * NCHUNK);
    const int tid   = threadIdx.x;

    // ---- stage this block's target slice ----
    const float* tb = tgt + (size_t)b * 3 * MTGT + slice * MSLICE;
    for (int p = tid; p < NPAIR; p += TPB) {
        int m = 2 * p;
        float x0 = tb[m],            x1 = tb[m + 1];
        float y0 = tb[MTGT + m],     y1 = tb[MTGT + m + 1];
        float z0 = tb[2 * MTGT + m], z1 = tb[2 * MTGT + m + 1];
        float w0 = fmaf(x0, x0, fmaf(y0, y0, z0 * z0));
        float w1 = fmaf(x1, x1, fmaf(y1, y1, z1 * z1));
        st[2 * p]     = make_float4(x0, x1, y0, y1);
        st[2 * p + 1] = make_float4(z0, z1, w0, w1);
    }
    __syncthreads();

    // ---- load 4 source points, broadcast -2*s into packed halves ----
    const float* sb = src + (size_t)b * 3 * NSRC;
    const int n0 = chunk * SRC_PER_BLK + tid;

    u64 X[SPT], Y[SPT], Z[SPT];
    float a0[SPT], a1[SPT];
    #pragma unroll
    for (int s = 0; s < SPT; s++) {
        int n = n0 + s * TPB;
        float sx = sb[n], sy = sb[NSRC + n], sz = sb[2 * NSRC + n];
        X[s] = pack2(-2.0f * sx, -2.0f * sx);
        Y[s] = pack2(-2.0f * sy, -2.0f * sy);
        Z[s] = pack2(-2.0f * sz, -2.0f * sz);
        a0[s] = 3.4e38f;
        a1[s] = 3.4e38f;
    }

    // ---- scan 512 target pairs; 2 targets x 4 sources per p ----
    #pragma unroll 4
    for (int p = 0; p < NPAIR; p++) {
        float4 A  = st[2 * p];
        float4 Bv = st[2 * p + 1];
        u64 x01 = pack2(A.x, A.y);
        u64 y01 = pack2(A.z, A.w);
        u64 z01 = pack2(Bv.x, Bv.y);
        u64 w01 = pack2(Bv.z, Bv.w);
        #pragma unroll
        for (int s = 0; s < SPT; s++) {
            u64 d = ffma2(x01, X[s], w01);
            d = ffma2(y01, Y[s], d);
            d = ffma2(z01, Z[s], d);
            float dl, dh;
            unpack2(d, dl, dh);
            a0[s] = fminf(a0[s], dl);
            a1[s] = fminf(a1[s], dh);
        }
    }

    // ---- store raw per-slice min (s2 added in finish kernel) ----
    float* gm = g_min + ((size_t)b * TSPLIT + slice) * NSRC;
    #pragma unroll
    for (int s = 0; s < SPT; s++)
        gm[n0 + s * TPB] = fminf(a0[s], a1[s]);
}

#define FTPB 256

__global__ void __launch_bounds__(FTPB)
finish_kernel(const float* __restrict__ src, float* __restrict__ out)
{
    const int b = blockIdx.x;
    const int tid = threadIdx.x;
    const float* sb = src + (size_t)b * 3 * NSRC;
    const float* gm = g_min + (size_t)b * TSPLIT * NSRC;

    float sum = 0.0f;
    for (int n = tid; n < NSRC; n += FTPB) {
        float mn = gm[n];
        #pragma unroll
        for (int k = 1; k < TSPLIT; k++)
            mn = fminf(mn, gm[k * NSRC + n]);
        float sx = sb[n], sy = sb[NSRC + n], sz = sb[2 * NSRC + n];
        float s2 = fmaf(sx, sx, fmaf(sy, sy, sz * sz));
        sum += mn + s2;
    }

    // deterministic block reduction
    #pragma unroll
    for (int off = 16; off > 0; off >>= 1)
        sum += __shfl_down_sync(0xFFFFFFFFu, sum, off);

    __shared__ float wsum[FTPB / 32];
    const int lane = tid & 31, wid = tid >> 5;
    if (lane == 0) wsum[wid] = sum;
    __syncthreads();
    if (tid == 0) {
        float s = 0.0f;
        #pragma unroll
        for (int i = 0; i < FTPB / 32; i++) s += wsum[i];
        out[b] = s * (1.0f / (float)(3 * NSRC));
    }
}

extern "C" void kernel_launch(void* const* d_in, const int* in_sizes, int n_in,
                              void* d_out, int out_size)
{
    const float* src = (const float*)d_in[0];   // [B,3,N]
    const float* tgt = (const float*)d_in[1];   // [B,3,M]
    float* out = (float*)d_out;                 // [B]

    nn_min_kernel<<<NBLOCKS, TPB>>>(src, tgt);
    finish_kernel<<<BATCH, FTPB>>>(src, out);
}

// round 6
// speedup vs baseline: 1.4687x; 1.1528x over previous
#include <cuda_runtime.h>
#include <math.h>

#define BATCH    8
#define NSRC     4096
#define MTGT     4096
#define TPB      128
#define SPT      4                       // sources per thread
#define SRC_PER_BLK (TPB * SPT)          // 512
#define NCHUNK   (NSRC / SRC_PER_BLK)    // 8
#define TSPLIT   8                       // target slices
#define MSLICE   (MTGT / TSPLIT)         // 512
#define NPAIR    (MSLICE / 2)            // 256
#define NBLOCKS  (BATCH * NCHUNK * TSPLIT) // 512

// Order-preserving uint-encoded min distance per (batch, source).
__device__ unsigned int g_min[BATCH * NSRC];

typedef unsigned long long u64;

__device__ __forceinline__ u64 pack2(float lo, float hi) {
    u64 r;
    asm("mov.b64 %0, {%1, %2};" : "=l"(r) : "f"(lo), "f"(hi));
    return r;
}
__device__ __forceinline__ void unpack2(u64 v, float& lo, float& hi) {
    asm("mov.b64 {%0, %1}, %2;" : "=f"(lo), "=f"(hi) : "l"(v));
}
// packed dual-FMA: d = a*b + c on both 32-bit halves (SASS FFMA2)
__device__ __forceinline__ u64 ffma2(u64 a, u64 b, u64 c) {
    u64 d;
    asm("fma.rn.f32x2 %0, %1, %2, %3;" : "=l"(d) : "l"(a), "l"(b), "l"(c));
    return d;
}

// float <-> order-preserving uint
__device__ __forceinline__ unsigned int fkey(float f) {
    unsigned int u = __float_as_uint(f);
    return (u & 0x80000000u) ? ~u : (u | 0x80000000u);
}
__device__ __forceinline__ float fdecode(unsigned int k) {
    unsigned int u = (k & 0x80000000u) ? (k ^ 0x80000000u) : ~k;
    return __uint_as_float(u);
}

__global__ void init_kernel()
{
    int i = blockIdx.x * blockDim.x + threadIdx.x;
    if (i < BATCH * NSRC) g_min[i] = 0xFFFFFFFFu;
}

__global__ void __launch_bounds__(TPB)
nn_min_kernel(const float* __restrict__ src, const float* __restrict__ tgt)
{
    // pair-interleaved targets: st[2p]={x0,x1,y0,y1}, st[2p+1]={z0,z1,w0,w1}
    __shared__ float4 st[2 * NPAIR];   // 8 KB

    const int bid   = blockIdx.x;
    const int slice = bid % TSPLIT;
    const int chunk = (bid / TSPLIT) % NCHUNK;
    const int b     = bid / (TSPLIT * NCHUNK);
    const int tid   = threadIdx.x;

    // ---- stage this block's target slice ----
    const float* tb = tgt + (size_t)b * 3 * MTGT + slice * MSLICE;
    for (int p = tid; p < NPAIR; p += TPB) {
        int m = 2 * p;
        float x0 = tb[m],            x1 = tb[m + 1];
        float y0 = tb[MTGT + m],     y1 = tb[MTGT + m + 1];
        float z0 = tb[2 * MTGT + m], z1 = tb[2 * MTGT + m + 1];
        float w0 = fmaf(x0, x0, fmaf(y0, y0, z0 * z0));
        float w1 = fmaf(x1, x1, fmaf(y1, y1, z1 * z1));
        st[2 * p]     = make_float4(x0, x1, y0, y1);
        st[2 * p + 1] = make_float4(z0, z1, w0, w1);
    }
    __syncthreads();

    // ---- load SPT source points, broadcast -2*s into packed halves ----
    const float* sb = src + (size_t)b * 3 * NSRC;
    const int n0 = chunk * SRC_PER_BLK + tid;

    u64 X[SPT], Y[SPT], Z[SPT];
    float s2[SPT], a0[SPT], a1[SPT];
    #pragma unroll
    for (int s = 0; s < SPT; s++) {
        int n = n0 + s * TPB;
        float sx = sb[n], sy = sb[NSRC + n], sz = sb[2 * NSRC + n];
        X[s] = pack2(-2.0f * sx, -2.0f * sx);
        Y[s] = pack2(-2.0f * sy, -2.0f * sy);
        Z[s] = pack2(-2.0f * sz, -2.0f * sz);
        s2[s] = fmaf(sx, sx, fmaf(sy, sy, sz * sz));
        a0[s] = 3.4e38f;
        a1[s] = 3.4e38f;
    }

    // ---- scan NPAIR target pairs; 2 targets x SPT sources per p ----
    #pragma unroll 4
    for (int p = 0; p < NPAIR; p++) {
        float4 A  = st[2 * p];
        float4 Bv = st[2 * p + 1];
        u64 x01 = pack2(A.x, A.y);
        u64 y01 = pack2(A.z, A.w);
        u64 z01 = pack2(Bv.x, Bv.y);
        u64 w01 = pack2(Bv.z, Bv.w);
        #pragma unroll
        for (int s = 0; s < SPT; s++) {
            u64 d = ffma2(x01, X[s], w01);
            d = ffma2(y01, Y[s], d);
            d = ffma2(z01, Z[s], d);
            float dl, dh;
            unpack2(d, dl, dh);
            a0[s] = fminf(a0[s], dl);
            a1[s] = fminf(a1[s], dh);
        }
    }

    // ---- deterministic cross-slice combine via atomicMin on ordered keys ----
    unsigned int* gm = g_min + (size_t)b * NSRC;
    #pragma unroll
    for (int s = 0; s < SPT; s++) {
        float mind = fminf(a0[s], a1[s]) + s2[s];
        atomicMin(&gm[n0 + s * TPB], fkey(mind));
    }
}

#define FTPB 256

__global__ void __launch_bounds__(FTPB)
finish_kernel(float* __restrict__ out)
{
    const int b = blockIdx.x;
    const int tid = threadIdx.x;
    const unsigned int* gm = g_min + (size_t)b * NSRC;

    float sum = 0.0f;
    #pragma unroll
    for (int n = tid; n < NSRC; n += FTPB)
        sum += fdecode(gm[n]);

    #pragma unroll
    for (int off = 16; off > 0; off >>= 1)
        sum += __shfl_down_sync(0xFFFFFFFFu, sum, off);

    __shared__ float wsum[FTPB / 32];
    const int lane = tid & 31, wid = tid >> 5;
    if (lane == 0) wsum[wid] = sum;
    __syncthreads();
    if (tid == 0) {
        float s = 0.0f;
        #pragma unroll
        for (int i = 0; i < FTPB / 32; i++) s += wsum[i];
        out[b] = s * (1.0f / (float)(3 * NSRC));
    }
}

extern "C" void kernel_launch(void* const* d_in, const int* in_sizes, int n_in,
                              void* d_out, int out_size)
{
    const float* src = (const float*)d_in[0];   // [B,3,N]
    const float* tgt = (const float*)d_in[1];   // [B,3,M]
    float* out = (float*)d_out;                 // [B]

    init_kernel<<<(BATCH * NSRC + 255) / 256, 256>>>();
    nn_min_kernel<<<NBLOCKS, TPB>>>(src, tgt);
    finish_kernel<<<BATCH, FTPB>>>(out);
}